// round 3
// baseline (speedup 1.0000x reference)
#include <cuda_runtime.h>
#include <math.h>
#include <stdint.h>

#define BQ    16
#define SEQ   512
#define NFch  32
#define ECH   128
#define HID   512
#define PRED  96
#define NFFT  64
#define HOPL  32
#define TOPM  32
#define WN    17
#define FB    33
#define LAMB  0.01f

#define ROWS  (BQ*NFch)      // 512  (b*32+n)
#define KTOT  (SEQ*ECH)      // 65536
#define KSPLIT 32
#define KCHUNK (KTOT/KSPLIT) // 2048

// ---------------- scratch (static device globals; no runtime alloc) --------
__device__ float2 g_c[ROWS*WN*TOPM];          // topk STFT values per (row,w,m)
__device__ int    g_fidx[ROWS*WN*TOPM];       // their frequency bins
__device__ float  g_v[6*WN*ECH];              // emb-contracted weight vectors
__device__ float  g_xo[(size_t)ROWS*KTOT];    // fused output (B,N,T,E) ~134MB
__device__ float  g_Hpart[(size_t)KSPLIT*ROWS*HID]; // split-K partials
__device__ float  g_H[ROWS*HID];              // reduced FC1 pre-activation

#define TWO_PI 6.28318530717958647692f
#define TWO_PI_D 6.28318530717958647692528676655900577

__device__ __forceinline__ int reflect_t(int j) {
    int t = j - 32;
    if (t < 0) t = -t;
    else if (t > SEQ-1) t = 2*(SEQ-1) - t;   // 1022 - t
    return t;
}

// ---------------- Kernel A: STFT (fp64-exact, f32-rounded) + top-32 --------
// Rank ORDER of the top-k matters downstream (xl/xr pairing), so the spectrum
// must match cuFFT's fp32 output as closely as possible: fp64 accumulation
// with exact twiddles, f32 frame products, correctly-rounded magnitudes.
__global__ void k_stft(const float* __restrict__ x) {
    __shared__ float  s_s[SEQ];
    __shared__ float  win_s[NFFT];
    __shared__ double cosd[NFFT], sind[NFFT];
    __shared__ float  Sre[WN*FB], Sim[WN*FB], Sab[WN*FB];
    int blk = blockIdx.x;           // b*32+n
    int b = blk >> 5, n = blk & 31;
    int tid = threadIdx.x;          // 128

    for (int t = tid; t < SEQ; t += 128) s_s[t] = x[(b*SEQ + t)*NFch + n];
    for (int t = tid; t < NFFT; t += 128) {
        float a = TWO_PI * (float)t / (float)NFFT;          // f32 arg, like reference
        win_s[t] = 0.5f - 0.5f * (float)cos((double)a);     // correctly-rounded cos
        double ad = TWO_PI_D * (double)t / 64.0;
        cosd[t] = cos(ad); sind[t] = sin(ad);
    }
    __syncthreads();

    for (int task = tid; task < WN*FB; task += 128) {
        int w = task / FB, f = task % FB;
        double re = 0.0, im = 0.0;
        for (int k = 0; k < NFFT; k++) {
            float v = s_s[reflect_t(w*HOPL + k)] * win_s[k];   // f32 like 'frames'
            int a = (f*k) & 63;                                 // exact angle index
            re = fma((double)v,  cosd[a], re);
            im = fma((double)v, -sind[a], im);
        }
        float rf = (float)re, imf = (float)im;
        Sre[task] = rf; Sim[task] = imf;
        Sab[task] = (float)sqrt((double)rf*rf + (double)imf*imf); // ~hypotf
    }
    __syncthreads();

    if (tid < WN) {
        int w = tid;
        float mag[FB]; bool used[FB];
        for (int f = 0; f < FB; f++) { mag[f] = Sab[w*FB+f]; used[f] = false; }
        int base = (blk*WN + w) * TOPM;
        for (int m = 0; m < TOPM; m++) {
            int best = 0; float bv = -1.f;
            for (int f = 0; f < FB; f++)
                if (!used[f] && mag[f] > bv) { bv = mag[f]; best = f; }  // stable: ties -> lower f
            used[best] = true;
            g_fidx[base+m] = best;
            g_c[base+m] = make_float2(Sre[w*FB+best], Sim[w*FB+best]);
        }
    }
}

// ---------------- Kernel B: v[k][w][f] = sum_e emb[e]*Wk[w,e,f] ------------
__global__ void k_vred(const float* __restrict__ emb,
                       const float* __restrict__ Wr,  const float* __restrict__ Wi,
                       const float* __restrict__ Wrl, const float* __restrict__ Wil,
                       const float* __restrict__ Wrr, const float* __restrict__ Wir) {
    int k = blockIdx.x / WN, w = blockIdx.x % WN;
    const float* Wm = (k==0)?Wr:(k==1)?Wi:(k==2)?Wrl:(k==3)?Wil:(k==4)?Wrr:Wir;
    int f = threadIdx.x;
    const float* base = Wm + (size_t)w*ECH*ECH + f;
    float acc = 0.f;
    #pragma unroll 4
    for (int e = 0; e < ECH; e++) acc = fmaf(emb[e], base[(size_t)e*ECH], acc);
    g_v[(k*WN + w)*ECH + f] = acc;
}

// ---------------- Kernel C: fused Y + scatter + irfft + OLA + bias ---------
#define SMEM_MAIN 94976
__global__ void k_main(const float* __restrict__ x, const float* __restrict__ emb,
                       const float* __restrict__ br, const float* __restrict__ bi) {
    extern __shared__ char smraw[];
    float2* tab     = (float2*)(smraw);
    float*  full_re = (float*) (smraw + 16896);
    float*  full_im = (float*) (smraw + 33792);
    float*  ring    = (float*) (smraw + 50688);
    float2* cc      = (float2*)(smraw + 83456);
    float*  vs      = (float*) (smraw + 87808);
    float*  win_s   = (float*) (smraw + 91904);
    float*  ienv    = (float*) (smraw + 92160);
    float*  emb_s   = (float*) (smraw + 92288);
    int*    fidx_s  = (int*)   (smraw + 92800);

    int tid = threadIdx.x;          // 256
    int blk = blockIdx.x;           // b*32+n
    int b = blk >> 5, n = blk & 31;

    for (int i = tid; i < FB*NFFT; i += 256) {
        int f = i >> 6, t = i & 63;
        double ad = TWO_PI_D * (double)((f*t) & 63) / 64.0;
        tab[i] = make_float2((float)cos(ad), (float)sin(ad));
    }
    for (int i = tid; i < NFFT; i += 256) {
        float a = TWO_PI * (float)i / (float)NFFT;
        win_s[i] = 0.5f - 0.5f * (float)cos((double)a);
    }
    for (int i = tid; i < HOPL; i += 256) {
        float a = TWO_PI * (float)i / (float)NFFT;
        float c = (float)cos((double)a);
        float w0 = 0.5f - 0.5f*c, w1 = 0.5f + 0.5f*c;
        ienv[i] = 1.0f / (w0*w0 + w1*w1);
    }
    for (int i = tid; i < ECH; i += 256) emb_s[i] = emb[i];
    for (int i = tid; i < WN*TOPM; i += 256) {
        cc[i]     = g_c[blk*WN*TOPM + i];
        fidx_s[i] = g_fidx[blk*WN*TOPM + i];
    }
    __syncthreads();

    int e0 = (tid & 31) << 2;       // e-fast across the warp -> broadcasts on tab
    int t0 = (tid >> 5) << 3;

    for (int w = 0; w < WN; w++) {
        for (int i = tid; i < 6*ECH; i += 256) {
            int k = i >> 7, e = i & 127;
            vs[i] = g_v[(k*WN + w)*ECH + e];
        }
        for (int i = tid; i < ECH; i += 256) {
            vs[6*ECH + i] = br[w*ECH + i];
            vs[7*ECH + i] = bi[w*ECH + i];
        }
        for (int i = tid; i < ECH*FB; i += 256) { full_re[i] = 0.f; full_im[i] = 0.f; }
        __syncthreads();

        for (int i = tid; i < ECH*TOPM; i += 256) {
            int m = i >> 7, e = i & 127;
            float2 c0 = cc[w*TOPM + m];
            float2 cl = (w > 0)    ? cc[(w-1)*TOPM + m] : make_float2(0.f,0.f);
            float2 cr = (w < WN-1) ? cc[(w+1)*TOPM + m] : make_float2(0.f,0.f);
            float vr  = vs[e],        vi  = vs[ECH+e];
            float vrl = vs[2*ECH+e],  vil = vs[3*ECH+e];
            float vrr = vs[4*ECH+e],  vir = vs[5*ECH+e];
            float ore = c0.x*vr - c0.y*vi + cl.x*vrl - cl.y*vil + cr.x*vrr - cr.y*vir + vs[6*ECH+e];
            float oim = c0.y*vr + c0.x*vi + cl.y*vrl + cl.x*vil + cr.y*vrr + cr.x*vir + vs[7*ECH+e];
            float yre = fmaxf(fmaxf(ore, 0.f) - LAMB, 0.f);
            float yim = fmaxf(fmaxf(oim, 0.f) - LAMB, 0.f);
            int f = fidx_s[w*TOPM + m];
            if (f == 0 || f == FB-1) {
                full_re[f*ECH + e] = yre * 0.015625f;   // 1/64, imag ignored by irfft
                full_im[f*ECH + e] = 0.f;
            } else {
                full_re[f*ECH + e] = yre * 0.03125f;    // 2/64
                full_im[f*ECH + e] = yim * 0.03125f;
            }
        }
        __syncthreads();

        float acc[4][8];
        #pragma unroll
        for (int jj = 0; jj < 4; jj++)
            #pragma unroll
            for (int kk = 0; kk < 8; kk++) acc[jj][kk] = 0.f;

        for (int f = 0; f < FB; f++) {
            float4 yr = *(const float4*)&full_re[f*ECH + e0];
            float4 yi = *(const float4*)&full_im[f*ECH + e0];
            float yra[4] = {yr.x, yr.y, yr.z, yr.w};
            float yia[4] = {yi.x, yi.y, yi.z, yi.w};
            #pragma unroll
            for (int kk = 0; kk < 8; kk++) {
                float2 ct = tab[f*NFFT + t0 + kk];
                #pragma unroll
                for (int jj = 0; jj < 4; jj++)
                    acc[jj][kk] = fmaf(yra[jj], ct.x, fmaf(-yia[jj], ct.y, acc[jj][kk]));
            }
        }

        #pragma unroll
        for (int kk = 0; kk < 8; kk++) {
            int t = t0 + kk;
            int slot = (w*HOPL + t) & 63;
            float wm = win_s[t];
            float4* rp = (float4*)&ring[slot*ECH + e0];
            float4 v;
            v.x = acc[0][kk]*wm; v.y = acc[1][kk]*wm;
            v.z = acc[2][kk]*wm; v.w = acc[3][kk]*wm;
            if (t < HOPL && w > 0) {
                float4 o = *rp;
                v.x += o.x; v.y += o.y; v.z += o.z; v.w += o.w;
            }
            *rp = v;
        }
        __syncthreads();

        if (w > 0) {
            for (int i = tid; i < HOPL*ECH; i += 256) {
                int r = i >> 7, e = i & 127;
                int t_out = (w-1)*HOPL + r;
                int slot = (w*HOPL + r) & 63;
                float val = ring[slot*ECH + e] * ienv[r]
                          + x[(b*SEQ + t_out)*NFch + n] * emb_s[e];
                g_xo[(size_t)blk*KTOT + t_out*ECH + e] = val;
            }
        }
        __syncthreads();
    }
}

// ---------------- Kernel D: FC1 split-K SGEMM (exact fp32) -----------------
__global__ void k_fc1(const float* __restrict__ w1) {
    __shared__ float As[8][128];
    __shared__ float Bs[8][128];
    int m0 = blockIdx.x * 128, n0 = blockIdx.y * 128;
    int kbase = blockIdx.z * KCHUNK;
    int tid = threadIdx.x;          // 256
    int ty = tid >> 4, tx = tid & 15;
    float acc[8][8];
    #pragma unroll
    for (int i = 0; i < 8; i++)
        #pragma unroll
        for (int j = 0; j < 8; j++) acc[i][j] = 0.f;

    int arow = tid >> 1, aq = tid & 1;
    for (int kc = kbase; kc < kbase + KCHUNK; kc += 8) {
        float4 a4 = *(const float4*)&g_xo[(size_t)(m0+arow)*KTOT + kc + aq*4];
        As[aq*4+0][arow] = a4.x; As[aq*4+1][arow] = a4.y;
        As[aq*4+2][arow] = a4.z; As[aq*4+3][arow] = a4.w;
        #pragma unroll
        for (int it = 0; it < 4; it++) {
            int i = tid + it*256;
            int k = i >> 7, nn = i & 127;
            Bs[k][nn] = w1[(size_t)(kc+k)*HID + n0 + nn];
        }
        __syncthreads();
        #pragma unroll
        for (int kk = 0; kk < 8; kk++) {
            float a[8], bv[8];
            #pragma unroll
            for (int i = 0; i < 8; i++) a[i]  = As[kk][ty*8+i];
            #pragma unroll
            for (int j = 0; j < 8; j++) bv[j] = Bs[kk][tx*8+j];
            #pragma unroll
            for (int i = 0; i < 8; i++)
                #pragma unroll
                for (int j = 0; j < 8; j++)
                    acc[i][j] = fmaf(a[i], bv[j], acc[i][j]);
        }
        __syncthreads();
    }
    size_t base = (size_t)blockIdx.z * (ROWS*HID);
    #pragma unroll
    for (int i = 0; i < 8; i++)
        #pragma unroll
        for (int j = 0; j < 8; j++)
            g_Hpart[base + (size_t)(m0+ty*8+i)*HID + n0 + tx*8+j] = acc[i][j];
}

__global__ void k_hred() {
    int i = blockIdx.x * 256 + threadIdx.x;
    if (i >= ROWS*HID) return;
    float s = 0.f;
    #pragma unroll
    for (int z = 0; z < KSPLIT; z++) s += g_Hpart[(size_t)z*(ROWS*HID) + i];
    g_H[i] = s;
}

// ---------------- Kernel E: leaky_relu + FC2 + output transpose ------------
__global__ void k_fc2(const float* __restrict__ b1, const float* __restrict__ w2,
                      const float* __restrict__ b2, float* __restrict__ out) {
    __shared__ float hrow[HID];
    int row = blockIdx.x;           // b*32+n
    int tid = threadIdx.x;          // 96
    for (int i = tid; i < HID; i += PRED) {
        float v = g_H[row*HID + i] + b1[i];
        hrow[i] = v > 0.f ? v : 0.01f * v;
    }
    __syncthreads();
    int b = row >> 5, n = row & 31;
    float acc = b2[tid];
    #pragma unroll 4
    for (int h = 0; h < HID; h++) acc = fmaf(hrow[h], w2[h*PRED + tid], acc);
    out[(b*PRED + tid)*NFch + n] = acc;
}

// ---------------------------------------------------------------------------
extern "C" void kernel_launch(void* const* d_in, const int* in_sizes, int n_in,
                              void* d_out, int out_size) {
    const float* x   = (const float*)d_in[0];
    const float* emb = (const float*)d_in[1];
    const float* br  = (const float*)d_in[8];
    const float* bi  = (const float*)d_in[9];
    const float* w1  = (const float*)d_in[10];
    const float* b1  = (const float*)d_in[11];
    const float* w2  = (const float*)d_in[12];
    const float* b2  = (const float*)d_in[13];
    float* out = (float*)d_out;

    cudaFuncSetAttribute(k_main, cudaFuncAttributeMaxDynamicSharedMemorySize, SMEM_MAIN);

    k_stft<<<ROWS, 128>>>(x);
    k_vred<<<6*WN, 128>>>(emb, (const float*)d_in[2], (const float*)d_in[3],
                          (const float*)d_in[4], (const float*)d_in[5],
                          (const float*)d_in[6], (const float*)d_in[7]);
    k_main<<<ROWS, 256, SMEM_MAIN>>>(x, emb, br, bi);
    k_fc1<<<dim3(4, 4, KSPLIT), 256>>>(w1);
    k_hred<<<(ROWS*HID + 255)/256, 256>>>();
    k_fc2<<<ROWS, PRED>>>(b1, w2, b2, out);
}